// round 1
// baseline (speedup 1.0000x reference)
#include <cuda_runtime.h>
#include <math.h>

#define D_DIM   768
#define R_DIM   64
#define E_NUM   4
#define NT      1029
#define BATCH   64
#define M_ROWS  (BATCH * NT)        /* 65856 */
#define T_TOKENS (BATCH * 1024)     /* 65536 MoE tokens */

#define BM 128
#define BK1 32
#define XS_STRIDE 130
#define WS_STRIDE 66

/* scratch: h / "full" buffer (in-place MoE update), transposed expert weights */
__device__ float g_h[(size_t)M_ROWS * R_DIM];
__device__ float g_WeT[E_NUM * R_DIM * R_DIM];

__device__ __forceinline__ float gelu_exact(float v) {
    return 0.5f * v * (1.0f + erff(v * 0.70710678118654752f));
}

/* ------------------------------------------------------------------ */
/* K0: WeT[e][r][s] = We[e][s][r]                                      */
__global__ void k0_transpose(const float* __restrict__ We) {
    int i = blockIdx.x * 256 + threadIdx.x;
    if (i < E_NUM * R_DIM * R_DIM) {
        int e = i >> 12;
        int r = (i >> 6) & 63;
        int s = i & 63;
        g_WeT[i] = We[(e << 12) + (s << 6) + r];
    }
}

/* ------------------------------------------------------------------ */
/* K1: g_h[m][n] = gelu( sum_k X[m][k] * Wd[n][k] ), n in [0,64)       */
__global__ __launch_bounds__(256) void k1_gemm_gelu(
    const float* __restrict__ X, const float* __restrict__ Wd)
{
    __shared__ float Xs[BK1 * XS_STRIDE];   /* [k][m], stride 130 */
    __shared__ float Ws[BK1 * WS_STRIDE];   /* [k][n], stride 66  */

    const int tid = threadIdx.x;
    const int tx = tid & 15;        /* n: 4 cols  */
    const int ty = tid >> 4;        /* m: 8 rows  */
    const int m0 = blockIdx.x * BM;

    float acc[8][4];
#pragma unroll
    for (int i = 0; i < 8; i++)
#pragma unroll
        for (int j = 0; j < 4; j++) acc[i][j] = 0.0f;

    for (int kt = 0; kt < D_DIM; kt += BK1) {
        /* X tile: 128 rows x 32 cols, transposed store */
#pragma unroll
        for (int j = 0; j < 4; j++) {
            int f = tid + 256 * j;
            int row = f >> 3;
            int kq = f & 7;
            int gr = m0 + row; if (gr >= M_ROWS) gr = M_ROWS - 1;
            float4 v = *(const float4*)(X + (size_t)gr * D_DIM + kt + kq * 4);
            Xs[(kq * 4 + 0) * XS_STRIDE + row] = v.x;
            Xs[(kq * 4 + 1) * XS_STRIDE + row] = v.y;
            Xs[(kq * 4 + 2) * XS_STRIDE + row] = v.z;
            Xs[(kq * 4 + 3) * XS_STRIDE + row] = v.w;
        }
        /* Wd tile: 64 rows(n) x 32 cols(k), transposed store */
#pragma unroll
        for (int j = 0; j < 2; j++) {
            int f = tid + 256 * j;
            int n = f >> 3;
            int kq = f & 7;
            float4 v = *(const float4*)(Wd + n * D_DIM + kt + kq * 4);
            Ws[(kq * 4 + 0) * WS_STRIDE + n] = v.x;
            Ws[(kq * 4 + 1) * WS_STRIDE + n] = v.y;
            Ws[(kq * 4 + 2) * WS_STRIDE + n] = v.z;
            Ws[(kq * 4 + 3) * WS_STRIDE + n] = v.w;
        }
        __syncthreads();

#pragma unroll
        for (int k = 0; k < BK1; k++) {
            float a[8], b[4];
#pragma unroll
            for (int i = 0; i < 4; i++) {
                float2 t2 = *(const float2*)&Xs[k * XS_STRIDE + ty * 8 + i * 2];
                a[i * 2] = t2.x; a[i * 2 + 1] = t2.y;
            }
#pragma unroll
            for (int i = 0; i < 2; i++) {
                float2 t2 = *(const float2*)&Ws[k * WS_STRIDE + tx * 4 + i * 2];
                b[i * 2] = t2.x; b[i * 2 + 1] = t2.y;
            }
#pragma unroll
            for (int i = 0; i < 8; i++)
#pragma unroll
                for (int j = 0; j < 4; j++)
                    acc[i][j] = fmaf(a[i], b[j], acc[i][j]);
        }
        __syncthreads();
    }

    /* epilogue: gelu + store h */
#pragma unroll
    for (int i = 0; i < 8; i++) {
        int gr = m0 + ty * 8 + i;
        if (gr < M_ROWS) {
            float4 o;
            o.x = gelu_exact(acc[i][0]);
            o.y = gelu_exact(acc[i][1]);
            o.z = gelu_exact(acc[i][2]);
            o.w = gelu_exact(acc[i][3]);
            *(float4*)(g_h + (size_t)gr * R_DIM + tx * 4) = o;
        }
    }
}

/* ------------------------------------------------------------------ */
/* K2: in-place MoE on t tokens (n >= 5): h += w * (We[e] h + be[e])   */
__global__ __launch_bounds__(256) void k2_moe(
    const float* __restrict__ Wg, const float* __restrict__ be)
{
    __shared__ float hs[8][4][64];
    const int tid = threadIdx.x;
    const int w = tid >> 5;
    const int lane = tid & 31;
    float* hw = &hs[w][0][0];

    for (int it = 0; it < 8; it++) {
        int tbase = blockIdx.x * 256 + it * 32 + w * 4;
        int g[4];
#pragma unroll
        for (int j = 0; j < 4; j++) {
            int t = tbase + j;
            g[j] = (t >> 10) * NT + 5 + (t & 1023);
            float2 v = *(const float2*)(g_h + (size_t)g[j] * R_DIM + lane * 2);
            *(float2*)&hw[j * 64 + lane * 2] = v;
        }
        __syncwarp();

        int   esel[4];
        float wsel[4];
#pragma unroll
        for (int j = 0; j < 4; j++) {
            float h0 = hw[j * 64 + lane];
            float h1 = hw[j * 64 + 32 + lane];
            float l0 = h0 * Wg[lane]        + h1 * Wg[32 + lane];
            float l1 = h0 * Wg[64 + lane]   + h1 * Wg[96 + lane];
            float l2 = h0 * Wg[128 + lane]  + h1 * Wg[160 + lane];
            float l3 = h0 * Wg[192 + lane]  + h1 * Wg[224 + lane];
#pragma unroll
            for (int o = 16; o > 0; o >>= 1) {
                l0 += __shfl_xor_sync(0xffffffffu, l0, o);
                l1 += __shfl_xor_sync(0xffffffffu, l1, o);
                l2 += __shfl_xor_sync(0xffffffffu, l2, o);
                l3 += __shfl_xor_sync(0xffffffffu, l3, o);
            }
            float mx = fmaxf(fmaxf(l0, l1), fmaxf(l2, l3));
            float e0 = __expf(l0 - mx);
            float e1 = __expf(l1 - mx);
            float e2 = __expf(l2 - mx);
            float e3 = __expf(l3 - mx);
            float ssum = e0 + e1 + e2 + e3;
            int am = 0; float bv = l0; float ev = e0;
            if (l1 > bv) { bv = l1; am = 1; ev = e1; }
            if (l2 > bv) { bv = l2; am = 2; ev = e2; }
            if (l3 > bv) { bv = l3; am = 3; ev = e3; }
            esel[j] = am;
            wsel[j] = ev / ssum;
        }

        float acc[4][2];
#pragma unroll
        for (int j = 0; j < 4; j++) { acc[j][0] = 0.0f; acc[j][1] = 0.0f; }
        const float* wp[4];
#pragma unroll
        for (int j = 0; j < 4; j++) wp[j] = g_WeT + (esel[j] << 12);

#pragma unroll 8
        for (int r = 0; r < 64; r++) {
#pragma unroll
            for (int j = 0; j < 4; j++) {
                float hr = hw[j * 64 + r];
                float2 wv = *(const float2*)(wp[j] + (r << 6) + lane * 2);
                acc[j][0] = fmaf(hr, wv.x, acc[j][0]);
                acc[j][1] = fmaf(hr, wv.y, acc[j][1]);
            }
        }

#pragma unroll
        for (int j = 0; j < 4; j++) {
            int e = esel[j];
            float b0 = be[(e << 6) + lane * 2];
            float b1 = be[(e << 6) + lane * 2 + 1];
            float2 hv = *(float2*)&hw[j * 64 + lane * 2];
            float2 o;
            o.x = hv.x + wsel[j] * (acc[j][0] + b0);
            o.y = hv.y + wsel[j] * (acc[j][1] + b1);
            *(float2*)(g_h + (size_t)g[j] * R_DIM + lane * 2) = o;
        }
        __syncwarp();
    }
}

/* ------------------------------------------------------------------ */
/* K3: out[m][d] = (sum_r full[m][r] * Wu[d][r]) * gamma[d]            */
__global__ __launch_bounds__(256) void k3_gemm_out(
    const float* __restrict__ Wu, const float* __restrict__ gamma,
    float* __restrict__ out)
{
    __shared__ float As[R_DIM * XS_STRIDE];  /* [k 0..63][m], stride 130 */
    __shared__ float Ws3[32 * WS_STRIDE];    /* [k 0..31][n], stride 66  */

    const int tid = threadIdx.x;
    const int tx = tid & 15;
    const int ty = tid >> 4;
    const int m0 = blockIdx.x * BM;

    /* load full A tile once: 128 rows x 64 k */
#pragma unroll
    for (int j = 0; j < 8; j++) {
        int f = tid + 256 * j;
        int row = f >> 4;
        int kq = f & 15;
        int gr = m0 + row; if (gr >= M_ROWS) gr = M_ROWS - 1;
        float4 v = *(const float4*)(g_h + (size_t)gr * R_DIM + kq * 4);
        As[(kq * 4 + 0) * XS_STRIDE + row] = v.x;
        As[(kq * 4 + 1) * XS_STRIDE + row] = v.y;
        As[(kq * 4 + 2) * XS_STRIDE + row] = v.z;
        As[(kq * 4 + 3) * XS_STRIDE + row] = v.w;
    }

    for (int c = 0; c < 12; c++) {
        int n0 = c * 64;
        float acc[8][4];
#pragma unroll
        for (int i = 0; i < 8; i++)
#pragma unroll
            for (int j = 0; j < 4; j++) acc[i][j] = 0.0f;

        for (int kh = 0; kh < 2; kh++) {
            __syncthreads();  /* protect Ws3 (and As on first pass) */
#pragma unroll
            for (int j = 0; j < 2; j++) {
                int f = tid + 256 * j;
                int n = f >> 3;
                int kq = f & 7;
                float4 v = *(const float4*)(Wu + (n0 + n) * R_DIM + kh * 32 + kq * 4);
                Ws3[(kq * 4 + 0) * WS_STRIDE + n] = v.x;
                Ws3[(kq * 4 + 1) * WS_STRIDE + n] = v.y;
                Ws3[(kq * 4 + 2) * WS_STRIDE + n] = v.z;
                Ws3[(kq * 4 + 3) * WS_STRIDE + n] = v.w;
            }
            __syncthreads();

#pragma unroll
            for (int k = 0; k < 32; k++) {
                int ka = kh * 32 + k;
                float a[8], b[4];
#pragma unroll
                for (int i = 0; i < 4; i++) {
                    float2 t2 = *(const float2*)&As[ka * XS_STRIDE + ty * 8 + i * 2];
                    a[i * 2] = t2.x; a[i * 2 + 1] = t2.y;
                }
#pragma unroll
                for (int i = 0; i < 2; i++) {
                    float2 t2 = *(const float2*)&Ws3[k * WS_STRIDE + tx * 4 + i * 2];
                    b[i * 2] = t2.x; b[i * 2 + 1] = t2.y;
                }
#pragma unroll
                for (int i = 0; i < 8; i++)
#pragma unroll
                    for (int j = 0; j < 4; j++)
                        acc[i][j] = fmaf(a[i], b[j], acc[i][j]);
            }
        }

        float4 gm = *(const float4*)(gamma + n0 + tx * 4);
#pragma unroll
        for (int i = 0; i < 8; i++) {
            int gr = m0 + ty * 8 + i;
            if (gr < M_ROWS) {
                float4 o;
                o.x = acc[i][0] * gm.x;
                o.y = acc[i][1] * gm.y;
                o.z = acc[i][2] * gm.z;
                o.w = acc[i][3] * gm.w;
                *(float4*)(out + (size_t)gr * D_DIM + n0 + tx * 4) = o;
            }
        }
    }
}

/* ------------------------------------------------------------------ */
extern "C" void kernel_launch(void* const* d_in, const int* in_sizes, int n_in,
                              void* d_out, int out_size) {
    const float* x     = (const float*)d_in[0];
    const float* Wd    = (const float*)d_in[1];
    const float* Wg    = (const float*)d_in[2];
    const float* We    = (const float*)d_in[3];
    const float* be    = (const float*)d_in[4];
    const float* Wu    = (const float*)d_in[5];
    const float* gamma = (const float*)d_in[6];
    float* out = (float*)d_out;

    k0_transpose<<<64, 256>>>(We);
    k1_gemm_gelu<<<(M_ROWS + BM - 1) / BM, 256>>>(x, Wd);
    k2_moe<<<T_TOKENS / 256, 256>>>(Wg, be);
    k3_gemm_out<<<(M_ROWS + BM - 1) / BM, 256>>>(Wu, gamma, out);
}